// round 14
// baseline (speedup 1.0000x reference)
#include <cuda_runtime.h>
#include <math.h>

#define NQ   10
#define DIM  1024
#define NP   64
#define DF   10
#define NL   5
#define NBLK 136          // 16*17/2 triangle tiles; single wave (<148 SMs)
#define NT   256
#define NSIMB (NP / 2)    // 32 sim blocks, 2 points each

#define TWOPI   6.2831853071795864769f
#define INV2PI  0.15915494309189533577f
#define EXS     12        // exchange stride in floats (48B, float4-aligned)
#define FXSCALE 1099511627776.0   // 2^40 fixed-point scale

// Scratch (no device allocations allowed)
__device__ __align__(16) float2 g_states[NP * DIM];   // psi(x_p), 512 KB
__device__ unsigned long long g_kp = 0ull, g_kk = 0ull;  // fixed-point accumulators
__device__ unsigned g_ready = 0;                      // sim-done counter (target NSIMB)
__device__ unsigned g_done  = 0;                      // gram-done ticket (target NBLK)

__device__ __forceinline__ void cmul(float ar, float ai, float br, float bi,
                                     float& cr, float& ci)
{
    cr = ar * br - ai * bi;
    ci = ar * bi + ai * br;
}

// ============================================================================
// Fused single kernel (R11 config + exact final-ring skip + THROTTLED POLL):
//  phase 1: blocks 0-31 simulate points 2b, 2b+1 (2 per thread, ILP).
//  wait:    throttled poll — ~300-cycle register-only LCG delay between
//           volatile reads of g_ready (unthrottled spin from 135 thread-0s
//           saturates the LTS slice owning g_ready and delays both the
//           releasing atomicAdd and the first gram loads).
//  phase 2: 136 blocks, one 4x4 triangle tile, 2 pairs/warp; block partials
//           llround'ed into int64 fixed-point global atomics (exact,
//           order-independent => deterministic).
//  tail:    last-ticket block, warp 0 only.
// ============================================================================
__global__ __launch_bounds__(NT) void fused_kernel(
    const float* __restrict__ data,     // (NP, DF)
    const float* __restrict__ labels,   // (NP,)
    const float* __restrict__ params,   // (NL, 2, NQ)
    float* __restrict__ out)
{
    __shared__ float Ug[2][NL][NQ][8];  // composed gates, per point
    __shared__ float phis[NL][NQ];      // ring angles (param-only)
    __shared__ float2 Cx[2][NL * 64];   // warp-exchange coefs [pt][l<<6|w<<3|pw]
    __shared__ float2 Lc[2][NL - 1][2][4][4]; // lane-pair coefs
    __shared__ float2 dfac[NL - 1][4][4];     // ring delta factors
    __shared__ __align__(16) float ebuf[2][2][NT * EXS];  // [pt][parity], 48 KB
    __shared__ double wacc[8][2];       // per-warp gram partials

    const int t    = threadIdx.x;
    const int lane = t & 31;
    const int w    = t >> 5;            // 8 warps

    // ---------------- phase 1: simulation (blocks 0-31, 2 points/thread) ----------------
    if (blockIdx.x < NSIMB) {
        const int pbase = 2 * blockIdx.x;

        // gate tables for both points + shared ring table
        for (int e = t; e < 2 * NL * NQ; e += NT) {
            const int pt = e / (NL * NQ);
            const int u  = e - pt * NL * NQ;
            const int l  = u / NQ, q = u % NQ;
            const float alpha = data[(pbase + pt) * DF + (NQ - 1 - q)];
            const float theta = params[l * 2 * NQ + q];
            float s, c, sa, ca;
            __sincosf(0.5f * theta, &s, &c);
            __sincosf(0.5f * alpha, &sa, &ca);
            const float INV_S2 = 0.70710678118654752440f;
            float* U = &Ug[pt][l][q][0];
            U[0] = (c - s) * ca * INV_S2;   U[1] = -(c + s) * sa * INV_S2;  // u00
            U[2] = (c + s) * ca * INV_S2;   U[3] =  (s - c) * sa * INV_S2;  // u01
            U[4] = (s + c) * ca * INV_S2;   U[5] =  (c - s) * sa * INV_S2;  // u10
            U[6] = (s - c) * ca * INV_S2;   U[7] = -(s + c) * sa * INV_S2;  // u11
            if (pt == 0) phis[l][q] = params[l * 2 * NQ + NQ + q];
        }
        __syncthreads();

        // warp-exchange coefficients Cx[pt][l][ww][pw] = U5*U6*U7 tensor product
        for (int e = t; e < 2 * NL * 64; e += NT) {
            const int pt2 = e / (NL * 64);
            const int u2  = e - pt2 * (NL * 64);
            const int l  = u2 >> 6;
            const int ww = (u2 >> 3) & 7;
            const int pw = u2 & 7;
            const int b5 = ww & 1, b6 = (ww >> 1) & 1, b7 = (ww >> 2) & 1;
            const float* U5 = &Ug[pt2][l][5][(2 * b5 + (pw & 1)) * 2];
            const float* U6 = &Ug[pt2][l][6][(2 * b6 + ((pw >> 1) & 1)) * 2];
            const float* U7 = &Ug[pt2][l][7][(2 * b7 + (pw >> 2)) * 2];
            float t1r, t1i, cr, ci;
            cmul(U5[0], U5[1], U6[0], U6[1], t1r, t1i);
            cmul(t1r, t1i, U7[0], U7[1], cr, ci);
            Cx[pt2][u2] = make_float2(cr, ci);
        }
        // lane-pair flat coefs: Lc[pt][l-1][pair][my2][mm]
        if (t < 256) {
            const int pt   = t >> 7;
            const int u    = t & 127;
            const int li   = u >> 5;          // 0..3 -> layer li+1
            const int pair = (u >> 4) & 1;
            const int my2  = (u >> 2) & 3;
            const int mm   = u & 3;
            const int q  = pair * 2;
            const int b0 = my2 & 1, b1 = (my2 >> 1) & 1;
            const int s0 = b0 ^ (mm & 1), s1 = b1 ^ ((mm >> 1) & 1);
            const float* A0 = &Ug[pt][li + 1][q][(b0 * 2 + s0) * 2];
            const float* A1 = &Ug[pt][li + 1][q + 1][(b1 * 2 + s1) * 2];
            float cr, ci;
            cmul(A0[0], A0[1], A1[0], A1[1], cr, ci);
            Lc[pt][li][pair][my2][mm] = make_float2(cr, ci);
        }
        // ring delta factors (final ring cancels exactly -> layers 0..NL-2 only)
        if (t < (NL - 1) * 16) {
            const int l  = t >> 4;
            const int bb = (t >> 2) & 3;    // (b7<<1)|b0
            const int r  = t & 3;
            const float b7 = (float)(bb >> 1), b0 = (float)(bb & 1);
            const float f8 = (float)(r & 1),  f9 = (float)(r >> 1);
            float d = b7 * (f8 - 0.5f) * phis[l][7]
                    + f8 * (f9 - 0.5f) * phis[l][8]
                    + f9 * (b0 - 0.5f) * phis[l][9];
            float s, c;
            __sincosf(d, &s, &c);
            dfac[l][bb][r] = make_float2(c, s);
        }

        float cring[7];
        #pragma unroll
        for (int m = 0; m < 7; ++m) {
            float bm  = (float)((t >> m) & 1);
            float bm1 = (float)((t >> (m + 1)) & 1);
            cring[m] = bm * (bm1 - 0.5f);
        }
        const int bb = (((t >> 7) & 1) << 1) | (t & 1);
        __syncthreads();

        float re[2][4], im[2][4];

        // layer 0 from |0>: amp = prod_q U_q[b_q][0]
        #pragma unroll
        for (int pt = 0; pt < 2; ++pt) {
            float cr = 1.f, ci = 0.f;
            #pragma unroll
            for (int q = 0; q < 8; ++q) {
                int b = (t >> q) & 1;
                const float* Uq = &Ug[pt][0][q][0];
                float nr, ni;
                cmul(cr, ci, Uq[b * 4], Uq[b * 4 + 1], nr, ni);
                cr = nr;  ci = ni;
            }
            float c8r[2], c8i[2];
            #pragma unroll
            for (int j = 0; j < 2; ++j)
                cmul(cr, ci, Ug[pt][0][8][j * 4], Ug[pt][0][8][j * 4 + 1],
                     c8r[j], c8i[j]);
            #pragma unroll
            for (int r = 0; r < 4; ++r)
                cmul(c8r[r & 1], c8i[r & 1],
                     Ug[pt][0][9][(r >> 1) * 4], Ug[pt][0][9][(r >> 1) * 4 + 1],
                     re[pt][r], im[pt][r]);
        }

        #pragma unroll 1
        for (int l = 0; ; ) {
            // ---- ring diagonal, layer l (final layer's ring cancels: skip) ----
            if (l < NL - 1) {
                float angT = 0.f;
                #pragma unroll
                for (int m = 0; m < 7; ++m) angT = fmaf(cring[m], phis[l][m], angT);
                angT = fmaf(-TWOPI, rintf(angT * INV2PI), angT);
                float sT, cT;
                __sincosf(angT, &sT, &cT);
                #pragma unroll
                for (int r = 0; r < 4; ++r) {
                    const float2 df = dfac[l][bb][r];
                    float fc, fs;
                    cmul(cT, sT, df.x, df.y, fc, fs);
                    #pragma unroll
                    for (int pt = 0; pt < 2; ++pt) {
                        float nr = re[pt][r] * fc - im[pt][r] * fs;
                        im[pt][r] = re[pt][r] * fs + im[pt][r] * fc;
                        re[pt][r] = nr;
                    }
                }
            }
            if (++l >= NL) break;

            // ---- lane qubit pairs (0,1) and (2,3): 4-way flat exchange ----
            #pragma unroll
            for (int pair = 0; pair < 2; ++pair) {
                const int q   = pair * 2;
                const int my2 = (lane >> q) & 3;
                #pragma unroll
                for (int pt = 0; pt < 2; ++pt) {
                    const float2 c0 = Lc[pt][l - 1][pair][my2][0];
                    const float2 c1 = Lc[pt][l - 1][pair][my2][1];
                    const float2 c2 = Lc[pt][l - 1][pair][my2][2];
                    const float2 c3 = Lc[pt][l - 1][pair][my2][3];
                    #pragma unroll
                    for (int r = 0; r < 4; ++r) {
                        float vr = re[pt][r], vi = im[pt][r];
                        float sr1 = __shfl_xor_sync(0xffffffffu, vr, 1 << q);
                        float si1 = __shfl_xor_sync(0xffffffffu, vi, 1 << q);
                        float sr2 = __shfl_xor_sync(0xffffffffu, vr, 2 << q);
                        float si2 = __shfl_xor_sync(0xffffffffu, vi, 2 << q);
                        float sr3 = __shfl_xor_sync(0xffffffffu, vr, 3 << q);
                        float si3 = __shfl_xor_sync(0xffffffffu, vi, 3 << q);
                        float nr = c0.x*vr  - c0.y*vi
                                 + c1.x*sr1 - c1.y*si1
                                 + c2.x*sr2 - c2.y*si2
                                 + c3.x*sr3 - c3.y*si3;
                        float ni = c0.x*vi  + c0.y*vr
                                 + c1.x*si1 + c1.y*sr1
                                 + c2.x*si2 + c2.y*sr2
                                 + c3.x*si3 + c3.y*sr3;
                        re[pt][r] = nr;  im[pt][r] = ni;
                    }
                }
            }
            // ---- lane qubit 4: butterfly ----
            {
                const int b = (lane >> 4) & 1;
                #pragma unroll
                for (int pt = 0; pt < 2; ++pt) {
                    const float* Uq = &Ug[pt][l][4][0];
                    const float ur = Uq[b * 6],     ui = Uq[b * 6 + 1];
                    const float vr = Uq[2 + b * 2], vi = Uq[3 + b * 2];
                    #pragma unroll
                    for (int r = 0; r < 4; ++r) {
                        float pre = __shfl_xor_sync(0xffffffffu, re[pt][r], 16);
                        float pim = __shfl_xor_sync(0xffffffffu, im[pt][r], 16);
                        float nr = ur * re[pt][r] - ui * im[pt][r] + vr * pre - vi * pim;
                        float ni = ur * im[pt][r] + ui * re[pt][r] + vr * pim + vi * pre;
                        re[pt][r] = nr;  im[pt][r] = ni;
                    }
                }
            }
            // ---- reg qubits 8, 9 ----
            #pragma unroll
            for (int pt = 0; pt < 2; ++pt) {
                const float* U8 = &Ug[pt][l][8][0];
                #pragma unroll
                for (int j = 0; j < 4; j += 2) {
                    float a0r = re[pt][j], a0i = im[pt][j];
                    float a1r = re[pt][j+1], a1i = im[pt][j+1];
                    re[pt][j]   = U8[0]*a0r - U8[1]*a0i + U8[2]*a1r - U8[3]*a1i;
                    im[pt][j]   = U8[0]*a0i + U8[1]*a0r + U8[2]*a1i + U8[3]*a1r;
                    re[pt][j+1] = U8[4]*a0r - U8[5]*a0i + U8[6]*a1r - U8[7]*a1i;
                    im[pt][j+1] = U8[4]*a0i + U8[5]*a0r + U8[6]*a1i + U8[7]*a1r;
                }
                const float* U9 = &Ug[pt][l][9][0];
                #pragma unroll
                for (int j = 0; j < 2; ++j) {
                    float a0r = re[pt][j], a0i = im[pt][j];
                    float a1r = re[pt][j+2], a1i = im[pt][j+2];
                    re[pt][j]   = U9[0]*a0r - U9[1]*a0i + U9[2]*a1r - U9[3]*a1i;
                    im[pt][j]   = U9[0]*a0i + U9[1]*a0r + U9[2]*a1i + U9[3]*a1r;
                    re[pt][j+2] = U9[4]*a0r - U9[5]*a0i + U9[6]*a1r - U9[7]*a1i;
                    im[pt][j+2] = U9[4]*a0i + U9[5]*a0r + U9[6]*a1i + U9[7]*a1r;
                }
            }
            // ---- warp qubits 5-7: flat 8-way exchange, 1 barrier ----
            {
                #pragma unroll
                for (int pt = 0; pt < 2; ++pt) {
                    float* my = &ebuf[pt][l & 1][t * EXS];
                    *(float4*)(my)     = make_float4(re[pt][0], re[pt][1],
                                                     re[pt][2], re[pt][3]);
                    *(float4*)(my + 4) = make_float4(im[pt][0], im[pt][1],
                                                     im[pt][2], im[pt][3]);
                }
                __syncthreads();
                #pragma unroll
                for (int pt = 0; pt < 2; ++pt) {
                    float nr[4] = {0.f,0.f,0.f,0.f}, ni[4] = {0.f,0.f,0.f,0.f};
                    const float2* cw = &Cx[pt][(l << 6) | (w << 3)];
                    #pragma unroll
                    for (int pw = 0; pw < 8; ++pw) {
                        const float* pr = &ebuf[pt][l & 1][((pw << 5) | lane) * EXS];
                        float4 vre = *(const float4*)(pr);
                        float4 vim = *(const float4*)(pr + 4);
                        const float cr = cw[pw].x, cc = cw[pw].y;
                        nr[0] += cr*vre.x - cc*vim.x;  ni[0] += cr*vim.x + cc*vre.x;
                        nr[1] += cr*vre.y - cc*vim.y;  ni[1] += cr*vim.y + cc*vre.y;
                        nr[2] += cr*vre.z - cc*vim.z;  ni[2] += cr*vim.z + cc*vre.z;
                        nr[3] += cr*vre.w - cc*vim.w;  ni[3] += cr*vim.w + cc*vre.w;
                    }
                    #pragma unroll
                    for (int r = 0; r < 4; ++r) { re[pt][r] = nr[r]; im[pt][r] = ni[r]; }
                }
            }
        }

        #pragma unroll
        for (int pt = 0; pt < 2; ++pt)
            #pragma unroll
            for (int r = 0; r < 4; ++r)
                g_states[(pbase + pt) * DIM + (r << 8) + t] =
                    make_float2(re[pt][r], im[pt][r]);

        __syncthreads();                 // all state writes done
        if (t == 0) {
            __threadfence();
            atomicAdd(&g_ready, 1u);
        }
    }

    // ---------------- wait: THROTTLED busy-poll ----------------
    if (t == 0) {
        if (*(volatile unsigned*)&g_ready < NSIMB) {
            // stagger first probe per block to desynchronize the herd
            unsigned x = (unsigned)(blockIdx.x * 37 + 1);
            #pragma unroll 1
            for (int i = 0; i < (int)(blockIdx.x & 63); ++i)
                x = x * 1664525u + 1013904223u;
            while (true) {
                // ~64 dependent IMADs (~300 cyc), register-only: no L2 traffic
                #pragma unroll 1
                for (int i = 0; i < 64; ++i)
                    x = x * 1664525u + 1013904223u;
                if (x == 0x7FFFFFFFu) __threadfence();   // opaque: keeps loop live
                if (*(volatile unsigned*)&g_ready >= NSIMB) break;
            }
        }
        __threadfence();
    }
    __syncthreads();

    // ---------------- phase 2: gram tile -> fixed-point atomics ----------------
    unsigned is_last = 0;
    {
        int rem = blockIdx.x, gi = 0;
        while (rem >= 16 - gi) { rem -= 16 - gi; ++gi; }
        const int gj = gi + rem;
        const int i  = gi * 4 + (w >> 1);
        const int j0 = gj * 4 + 2 * (w & 1);
        const double f = (gi == gj) ? 1.0 : 2.0;

        const float2* __restrict__ A  = g_states + i * DIM;
        const float2* __restrict__ B0 = g_states + j0 * DIM;
        const float2* __restrict__ B1 = g_states + (j0 + 1) * DIM;

        float r0 = 0.f, i0a = 0.f, r1 = 0.f, i1a = 0.f;
        #pragma unroll 8
        for (int kk = 0; kk < 16; ++kk) {
            const int k = kk * 64 + lane * 2;
            float4 a  = *(const float4*)&A[k];
            float4 b0 = *(const float4*)&B0[k];
            float4 b1 = *(const float4*)&B1[k];
            r0  += b0.x*a.x + b0.y*a.y + b0.z*a.z + b0.w*a.w;
            i0a += b0.x*a.y - b0.y*a.x + b0.z*a.w - b0.w*a.z;
            r1  += b1.x*a.x + b1.y*a.y + b1.z*a.z + b1.w*a.w;
            i1a += b1.x*a.y - b1.y*a.x + b1.z*a.w - b1.w*a.z;
        }
        #pragma unroll
        for (int off = 16; off; off >>= 1) {
            r0  += __shfl_down_sync(0xffffffffu, r0,  off);
            i0a += __shfl_down_sync(0xffffffffu, i0a, off);
            r1  += __shfl_down_sync(0xffffffffu, r1,  off);
            i1a += __shfl_down_sync(0xffffffffu, i1a, off);
        }
        if (lane == 0) {
            double k0 = (double)r0 * r0 + (double)i0a * i0a;
            double k1 = (double)r1 * r1 + (double)i1a * i1a;
            double li  = (double)labels[i];
            double lj0 = (double)labels[j0];
            double lj1 = (double)labels[j0 + 1];
            wacc[w][0] = f * (li * lj0 * k0 + li * lj1 * k1);
            wacc[w][1] = f * (k0 * k0 + k1 * k1);
        }
        __syncthreads();
        if (t == 0) {
            double kp = 0.0, kk = 0.0;
            #pragma unroll
            for (int ww = 0; ww < 8; ++ww) { kp += wacc[ww][0]; kk += wacc[ww][1]; }
            // exact integer accumulation: order-independent => deterministic
            long long kpi = llround(kp * FXSCALE);
            long long kki = llround(kk * FXSCALE);
            atomicAdd(&g_kp, (unsigned long long)kpi);
            atomicAdd(&g_kk, (unsigned long long)kki);
            __threadfence();
            is_last = (atomicInc(&g_done, NBLK - 1) == NBLK - 1) ? 1u : 0u;
        }
    }

    // ---------------- tail: last block, warp 0 only (no block barrier) ----------------
    if (w == 0) {
        is_last = __shfl_sync(0xffffffffu, is_last, 0);
        if (is_last) {
            __threadfence();
            float l0 = labels[lane], l1 = labels[lane + 32];
            double sl2 = (double)(l0 * l0 + l1 * l1);
            #pragma unroll
            for (int off = 16; off; off >>= 1)
                sl2 += __shfl_down_sync(0xffffffffu, sl2, off);
            if (lane == 0) {
                double kp = (double)(long long)(*(volatile unsigned long long*)&g_kp) / FXSCALE;
                double kk = (double)(long long)(*(volatile unsigned long long*)&g_kk) / FXSCALE;
                out[0] = (float)(kp / sqrt(kk * sl2 * sl2));
                g_kp = 0ull;  g_kk = 0ull;   // reset for next graph replay
                g_ready = 0;  g_done = 0;
                __threadfence();
            }
        }
    }
}

// ----------------------------------------------------------------------------
extern "C" void kernel_launch(void* const* d_in, const int* in_sizes, int n_in,
                              void* d_out, int out_size)
{
    const float* data   = (const float*)d_in[0];   // (64, 10)
    const float* labels = (const float*)d_in[1];   // (64,)
    const float* params = (const float*)d_in[2];   // (5, 2, 10)
    float* out = (float*)d_out;

    fused_kernel<<<NBLK, NT>>>(data, labels, params, out);
}

// round 15
// speedup vs baseline: 1.1116x; 1.1116x over previous
#include <cuda_runtime.h>
#include <math.h>

#define NQ   10
#define DIM  1024
#define NP   64
#define DF   10
#define NL   5
#define NBLK 136          // 16*17/2 triangle tiles; single wave (<148 SMs)
#define NT   256

#define TWOPI   6.2831853071795864769f
#define INV2PI  0.15915494309189533577f
#define EXS     12        // exchange stride in floats (48B, float4-aligned)

// Scratch (no device allocations allowed)
__device__ __align__(16) float2 g_states[NP * DIM];   // psi(x_p), 512 KB
__device__ __align__(16) double2 g_part[NBLK];        // per-block (kp, kk)
__device__ unsigned g_ready = 0;                      // sim-done counter (target 64)
__device__ unsigned g_done  = 0;                      // gram-done ticket (target NBLK)

__device__ __forceinline__ void cmul(float ar, float ai, float br, float bi,
                                     float& cr, float& ci)
{
    cr = ar * br - ai * bi;
    ci = ar * bi + ai * br;
}

// ============================================================================
// Fused single kernel — exact R8 champion config + final-ring skip:
//  phase 1: blocks 0-63 simulate psi(x_p), one point per block, A=4/thread.
//           The FINAL layer's crz-ring diagonal is skipped: it is the same
//           unitary diagonal for every point (param-only) and cancels
//           exactly in every |<a|b>|^2 of the Gram matrix.
//  wait:    plain busy-poll until g_ready == 64 (fastest measured).
//  phase 2: 136 blocks, one 4x4 triangle tile, 2 pairs/warp.
//  tail:    last block (ticket), warp 0 only, fixed-order 136-partial reduce.
// ============================================================================
__global__ __launch_bounds__(NT) void fused_kernel(
    const float* __restrict__ data,     // (NP, DF)
    const float* __restrict__ labels,   // (NP,)
    const float* __restrict__ params,   // (NL, 2, NQ)
    float* __restrict__ out)
{
    __shared__ float Ug[NL][NQ][8];     // composed gates U = RY*RZ*H (incl 1/sqrt2)
    __shared__ float phis[NL][NQ];
    __shared__ float2 Cx[NL * 64];      // exchange coefs [l][w][pw]
    __shared__ __align__(16) float ebuf[2][NT * EXS];   // 24 KB
    __shared__ double wacc[8][2];       // per-warp gram partials
    __shared__ unsigned s_last;

    const int p    = blockIdx.x;
    const int t    = threadIdx.x;
    const int lane = t & 31;
    const int w    = t >> 5;            // 8 warps

    // ---------------- phase 1: simulation (blocks 0-63) ----------------
    if (p < NP) {
        if (t < NL * NQ) {
            const int l = t / NQ, q = t % NQ;
            const float alpha = data[p * DF + (NQ - 1 - q)];
            const float theta = params[l * 2 * NQ + q];
            float s, c, sa, ca;
            __sincosf(0.5f * theta, &s, &c);
            __sincosf(0.5f * alpha, &sa, &ca);
            const float INV_S2 = 0.70710678118654752440f;
            float* U = &Ug[l][q][0];
            U[0] = (c - s) * ca * INV_S2;   U[1] = -(c + s) * sa * INV_S2;  // u00
            U[2] = (c + s) * ca * INV_S2;   U[3] =  (s - c) * sa * INV_S2;  // u01
            U[4] = (s + c) * ca * INV_S2;   U[5] =  (c - s) * sa * INV_S2;  // u10
            U[6] = (s - c) * ca * INV_S2;   U[7] = -(s + c) * sa * INV_S2;  // u11
            phis[l][q] = params[l * 2 * NQ + NQ + q];
        }
        __syncthreads();

        // exchange coefficients Cx[l][ww][pw] = U5[b5][pw0]*U6[b6][pw1]*U7[b7][pw2]
        for (int e = t; e < NL * 64; e += NT) {
            const int l  = e >> 6;
            const int ww = (e >> 3) & 7;
            const int pw = e & 7;
            const int b5 = ww & 1, b6 = (ww >> 1) & 1, b7 = (ww >> 2) & 1;
            const float* U5 = &Ug[l][5][(2 * b5 + (pw & 1)) * 2];
            const float* U6 = &Ug[l][6][(2 * b6 + ((pw >> 1) & 1)) * 2];
            const float* U7 = &Ug[l][7][(2 * b7 + (pw >> 2)) * 2];
            float t1r, t1i, cr, ci;
            cmul(U5[0], U5[1], U6[0], U6[1], t1r, t1i);
            cmul(t1r, t1i, U7[0], U7[1], cr, ci);
            Cx[e] = make_float2(cr, ci);
        }

        float cring[7];
        #pragma unroll
        for (int m = 0; m < 7; ++m) {
            float bm  = (float)((t >> m) & 1);
            float bm1 = (float)((t >> (m + 1)) & 1);
            cring[m] = bm * (bm1 - 0.5f);
        }
        const float c7  = (float)((t >> 7) & 1);
        const float c9a = (float)(t & 1) - 0.5f;
        __syncthreads();

        float re[4], im[4];

        // layer 0 from |0>: amp = prod_q U_q[b_q][0]
        {
            float cr = 1.f, ci = 0.f;
            #pragma unroll
            for (int q = 0; q < 8; ++q) {
                int b = (t >> q) & 1;
                const float* Uq = &Ug[0][q][0];
                float nr, ni;
                cmul(cr, ci, Uq[b * 4], Uq[b * 4 + 1], nr, ni);
                cr = nr;  ci = ni;
            }
            float c8r[2], c8i[2];
            #pragma unroll
            for (int j = 0; j < 2; ++j)
                cmul(cr, ci, Ug[0][8][j * 4], Ug[0][8][j * 4 + 1], c8r[j], c8i[j]);
            #pragma unroll
            for (int r = 0; r < 4; ++r)
                cmul(c8r[r & 1], c8i[r & 1],
                     Ug[0][9][(r >> 1) * 4], Ug[0][9][(r >> 1) * 4 + 1],
                     re[r], im[r]);
        }

        #pragma unroll 1
        for (int l = 0; ; ) {
            // crz ring diagonal, layer l — FINAL layer's ring cancels: skip
            if (l < NL - 1) {
                float angT = 0.f;
                #pragma unroll
                for (int m = 0; m < 7; ++m) angT = fmaf(cring[m], phis[l][m], angT);
                const float p7 = phis[l][7], p8 = phis[l][8], p9 = phis[l][9];
                #pragma unroll
                for (int r = 0; r < 4; ++r) {
                    float f8 = (float)(r & 1), f9 = (float)(r >> 1);
                    float ang = angT;
                    ang = fmaf(c7 * (f8 - 0.5f), p7, ang);
                    ang = fmaf(f8 * (f9 - 0.5f), p8, ang);
                    ang = fmaf(f9 * c9a,         p9, ang);
                    ang = fmaf(-TWOPI, rintf(ang * INV2PI), ang);
                    float s, c;
                    __sincosf(ang, &s, &c);
                    float nr = re[r] * c - im[r] * s;
                    im[r]    = re[r] * s + im[r] * c;
                    re[r]    = nr;
                }
            }
            if (++l >= NL) break;

            // lane qubits 0-4 (shfl butterflies)
            #pragma unroll
            for (int q = 0; q < 5; ++q) {
                const int b = (lane >> q) & 1;
                const float* Uq = &Ug[l][q][0];
                const float ur = Uq[b * 6],     ui = Uq[b * 6 + 1];
                const float vr = Uq[2 + b * 2], vi = Uq[3 + b * 2];
                #pragma unroll
                for (int r = 0; r < 4; ++r) {
                    float pre = __shfl_xor_sync(0xffffffffu, re[r], 1 << q);
                    float pim = __shfl_xor_sync(0xffffffffu, im[r], 1 << q);
                    float nr = ur * re[r] - ui * im[r] + vr * pre - vi * pim;
                    float ni = ur * im[r] + ui * re[r] + vr * pim + vi * pre;
                    re[r] = nr;  im[r] = ni;
                }
            }
            // reg qubits 8, 9
            {
                const float* U8 = &Ug[l][8][0];
                #pragma unroll
                for (int j = 0; j < 4; j += 2) {
                    float a0r = re[j], a0i = im[j], a1r = re[j+1], a1i = im[j+1];
                    re[j]   = U8[0]*a0r - U8[1]*a0i + U8[2]*a1r - U8[3]*a1i;
                    im[j]   = U8[0]*a0i + U8[1]*a0r + U8[2]*a1i + U8[3]*a1r;
                    re[j+1] = U8[4]*a0r - U8[5]*a0i + U8[6]*a1r - U8[7]*a1i;
                    im[j+1] = U8[4]*a0i + U8[5]*a0r + U8[6]*a1i + U8[7]*a1r;
                }
                const float* U9 = &Ug[l][9][0];
                #pragma unroll
                for (int j = 0; j < 2; ++j) {
                    float a0r = re[j], a0i = im[j], a1r = re[j+2], a1i = im[j+2];
                    re[j]   = U9[0]*a0r - U9[1]*a0i + U9[2]*a1r - U9[3]*a1i;
                    im[j]   = U9[0]*a0i + U9[1]*a0r + U9[2]*a1i + U9[3]*a1r;
                    re[j+2] = U9[4]*a0r - U9[5]*a0i + U9[6]*a1r - U9[7]*a1i;
                    im[j+2] = U9[4]*a0i + U9[5]*a0r + U9[6]*a1i + U9[7]*a1r;
                }
            }
            // warp qubits 5-7: flat 8-way exchange (precomputed coefs)
            {
                float* my = &ebuf[l & 1][t * EXS];
                *(float4*)(my)     = make_float4(re[0], re[1], re[2], re[3]);
                *(float4*)(my + 4) = make_float4(im[0], im[1], im[2], im[3]);
                __syncthreads();
                float nr[4] = {0.f,0.f,0.f,0.f}, ni[4] = {0.f,0.f,0.f,0.f};
                const float2* cw = &Cx[(l << 6) | (w << 3)];
                #pragma unroll
                for (int pw = 0; pw < 8; ++pw) {
                    const float* pr = &ebuf[l & 1][((pw << 5) | lane) * EXS];
                    float4 vre = *(const float4*)(pr);
                    float4 vim = *(const float4*)(pr + 4);
                    const float cr = cw[pw].x, cc = cw[pw].y;
                    nr[0] += cr*vre.x - cc*vim.x;  ni[0] += cr*vim.x + cc*vre.x;
                    nr[1] += cr*vre.y - cc*vim.y;  ni[1] += cr*vim.y + cc*vre.y;
                    nr[2] += cr*vre.z - cc*vim.z;  ni[2] += cr*vim.z + cc*vre.z;
                    nr[3] += cr*vre.w - cc*vim.w;  ni[3] += cr*vim.w + cc*vre.w;
                }
                #pragma unroll
                for (int r = 0; r < 4; ++r) { re[r] = nr[r]; im[r] = ni[r]; }
            }
        }

        #pragma unroll
        for (int r = 0; r < 4; ++r)
            g_states[p * DIM + (r << 8) + t] = make_float2(re[r], im[r]);

        __syncthreads();                 // all state writes done
        if (t == 0) {
            __threadfence();
            atomicAdd(&g_ready, 1u);
        }
    }

    // ---------------- wait: busy-poll (R8 style, fastest measured) ----------------
    if (t == 0) {
        while (*(volatile unsigned*)&g_ready < NP) { }
        __threadfence();
    }
    __syncthreads();

    // ---------------- phase 2: gram tile + local KTA contribution ----------------
    {
        int rem = blockIdx.x, gi = 0;
        while (rem >= 16 - gi) { rem -= 16 - gi; ++gi; }
        const int gj = gi + rem;
        const int i  = gi * 4 + (w >> 1);
        const int j0 = gj * 4 + 2 * (w & 1);
        const double f = (gi == gj) ? 1.0 : 2.0;

        const float2* __restrict__ A  = g_states + i * DIM;
        const float2* __restrict__ B0 = g_states + j0 * DIM;
        const float2* __restrict__ B1 = g_states + (j0 + 1) * DIM;

        float r0 = 0.f, i0a = 0.f, r1 = 0.f, i1a = 0.f;
        #pragma unroll 8
        for (int kk = 0; kk < 16; ++kk) {
            const int k = kk * 64 + lane * 2;
            float4 a  = *(const float4*)&A[k];
            float4 b0 = *(const float4*)&B0[k];
            float4 b1 = *(const float4*)&B1[k];
            r0  += b0.x*a.x + b0.y*a.y + b0.z*a.z + b0.w*a.w;
            i0a += b0.x*a.y - b0.y*a.x + b0.z*a.w - b0.w*a.z;
            r1  += b1.x*a.x + b1.y*a.y + b1.z*a.z + b1.w*a.w;
            i1a += b1.x*a.y - b1.y*a.x + b1.z*a.w - b1.w*a.z;
        }
        #pragma unroll
        for (int off = 16; off; off >>= 1) {
            r0  += __shfl_down_sync(0xffffffffu, r0,  off);
            i0a += __shfl_down_sync(0xffffffffu, i0a, off);
            r1  += __shfl_down_sync(0xffffffffu, r1,  off);
            i1a += __shfl_down_sync(0xffffffffu, i1a, off);
        }
        if (lane == 0) {
            double k0 = (double)r0 * r0 + (double)i0a * i0a;
            double k1 = (double)r1 * r1 + (double)i1a * i1a;
            double li  = (double)labels[i];
            double lj0 = (double)labels[j0];
            double lj1 = (double)labels[j0 + 1];
            wacc[w][0] = f * (li * lj0 * k0 + li * lj1 * k1);
            wacc[w][1] = f * (k0 * k0 + k1 * k1);
        }
        __syncthreads();
        if (t == 0) {
            double kp = 0.0, kk = 0.0;
            #pragma unroll
            for (int ww = 0; ww < 8; ++ww) { kp += wacc[ww][0]; kk += wacc[ww][1]; }
            g_part[blockIdx.x] = make_double2(kp, kk);
            __threadfence();
            s_last = (atomicInc(&g_done, NBLK - 1) == NBLK - 1) ? 1u : 0u;
        }
    }
    __syncthreads();

    // ---------------- tail: last block, warp 0 only, fixed-order reduce ----------------
    if (s_last && w == 0) {
        __threadfence();
        double kp = 0.0, kk = 0.0;
        #pragma unroll
        for (int e = lane; e < NBLK; e += 32) {     // fixed order per lane
            double2 v = g_part[e];
            kp += v.x;  kk += v.y;
        }
        float l0 = labels[lane], l1 = labels[lane + 32];
        double sl2 = (double)(l0 * l0 + l1 * l1);
        #pragma unroll
        for (int off = 16; off; off >>= 1) {
            kp  += __shfl_down_sync(0xffffffffu, kp,  off);
            kk  += __shfl_down_sync(0xffffffffu, kk,  off);
            sl2 += __shfl_down_sync(0xffffffffu, sl2, off);
        }
        if (lane == 0) {
            out[0] = (float)(kp / sqrt(kk * sl2 * sl2));
            g_ready = 0;          // reset for next graph replay
            g_done  = 0;
            __threadfence();
        }
    }
}

// ----------------------------------------------------------------------------
extern "C" void kernel_launch(void* const* d_in, const int* in_sizes, int n_in,
                              void* d_out, int out_size)
{
    const float* data   = (const float*)d_in[0];   // (64, 10)
    const float* labels = (const float*)d_in[1];   // (64,)
    const float* params = (const float*)d_in[2];   // (5, 2, 10)
    float* out = (float*)d_out;

    fused_kernel<<<NBLK, NT>>>(data, labels, params, out);
}